// round 2
// baseline (speedup 1.0000x reference)
#include <cuda_runtime.h>
#include <math.h>

#define BATCH 256
#define SEQ   256
#define NIN   512
#define HD    1024
#define MOUT  512
#define FOURH (4*HD)          // 4096

// ---------------- static device scratch (no runtime allocation allowed) ----------------
__device__ float    g_h[BATCH*HD];              // hidden state  [256,1024]
__device__ float    g_c[BATCH*HD];              // cell state    [256,1024]
__device__ float    g_pre[SEQ*BATCH*FOURH];     // precomputed x-projections+bias [s][b][r], r=j*4+gate
__device__ unsigned g_Whi[FOURH*HD];            // tf32 hi of permuted Wh  [r][k]
__device__ unsigned g_Wlo[FOURH*HD];            // tf32 lo
__device__ unsigned g_Wxhi[FOURH*NIN];          // tf32 hi of permuted Wx  [r][k]
__device__ unsigned g_Wxlo[FOURH*NIN];          // tf32 lo
__device__ float    g_bperm[FOURH];             // permuted biases

// ---------------- helpers ----------------
__device__ __forceinline__ unsigned f2tf32(float f){
    unsigned u; asm("cvt.rna.tf32.f32 %0, %1;" : "=r"(u) : "f"(f)); return u;
}

__device__ __forceinline__ void mma_tf32(float c[4], const unsigned a[4], const unsigned b[2]){
    asm volatile("mma.sync.aligned.m16n8k8.row.col.f32.tf32.tf32.f32 "
        "{%0,%1,%2,%3}, {%4,%5,%6,%7}, {%8,%9}, {%0,%1,%2,%3};"
        : "+f"(c[0]), "+f"(c[1]), "+f"(c[2]), "+f"(c[3])
        : "r"(a[0]), "r"(a[1]), "r"(a[2]), "r"(a[3]), "r"(b[0]), "r"(b[1]));
}

// ---------------- state init ----------------
__global__ void zero_state_kernel(){
    int idx = blockIdx.x*blockDim.x + threadIdx.x;
    if (idx < BATCH*HD){ g_h[idx] = 0.f; g_c[idx] = 0.f; }
}

// ---------------- weight prep: permute rows to r=j*4+gate, split into tf32 hi/lo ----------------
// Wh part: [4096 x 1024]
__global__ void prep_wh_kernel(
    const float* __restrict__ Wgh, const float* __restrict__ Wih,
    const float* __restrict__ Wfh, const float* __restrict__ Woh)
{
    int idx = blockIdx.x*blockDim.x + threadIdx.x;
    if (idx >= FOURH*HD) return;
    int r = idx >> 10;             // permuted row
    int k = idx & (HD-1);
    int j = r >> 2;
    int gate = r & 3;
    const float* W = (gate==0)?Wgh:(gate==1)?Wih:(gate==2)?Wfh:Woh;
    float w = W[j*HD + k];
    unsigned hi = f2tf32(w);
    g_Whi[idx] = hi;
    g_Wlo[idx] = f2tf32(w - __uint_as_float(hi));
}

// Wx part: [4096 x 512] + biases
__global__ void prep_wx_kernel(
    const float* __restrict__ Wgx, const float* __restrict__ Wix,
    const float* __restrict__ Wfx, const float* __restrict__ Wox,
    const float* __restrict__ bg,  const float* __restrict__ bi,
    const float* __restrict__ bf,  const float* __restrict__ bo)
{
    int idx = blockIdx.x*blockDim.x + threadIdx.x;
    if (idx >= FOURH*NIN) return;
    int r = idx >> 9;
    int k = idx & (NIN-1);
    int j = r >> 2;
    int gate = r & 3;
    const float* W = (gate==0)?Wgx:(gate==1)?Wix:(gate==2)?Wfx:Wox;
    float w = W[j*NIN + k];
    unsigned hi = f2tf32(w);
    g_Wxhi[idx] = hi;
    g_Wxlo[idx] = f2tf32(w - __uint_as_float(hi));
    if (k == 0){
        const float* B = (gate==0)?bg:(gate==1)?bi:(gate==2)?bf:bo;
        g_bperm[r] = B[j];
    }
}

// ---------------- tiling constants ----------------
#define BM 128
#define BN 64
#define BK 16
#define SPAD 20                // padded smem row stride (words)
#define ZPAD 68                // padded z-tile row stride (words)

// smem pool layout (words):
//   mainloop:  As_hi[0..2560) As_lo[2560..5120) Bs_hi[5120..6400) Bs_lo[6400..7680)
//   epilogue:  zsm[0..128*68) (aliased, after final __syncthreads)
#define POOL_WORDS (BM*ZPAD)   // 8704 words = 34816 B  (>= 7680)

// =====================================================================================
// Input projection: pre[s][b][r] = x[(b,s),:] @ WxP^T + bperm   (3xTF32 split)
// M = B*S = 65536 rows (m = b*SEQ + s), N = 4096, K = 512
// =====================================================================================
__global__ __launch_bounds__(256) void input_proj_kernel(const float* __restrict__ x)
{
    __shared__ unsigned pool[7680];
    unsigned* As_hi = pool;
    unsigned* As_lo = pool + 2560;
    unsigned* Bs_hi = pool + 5120;
    unsigned* Bs_lo = pool + 6400;

    const int tid  = threadIdx.x;
    const int wid  = tid >> 5;
    const int lane = tid & 31;
    const int warpM = wid & 3;
    const int warpN = wid >> 2;
    const int grp = lane >> 2;
    const int tg  = lane & 3;
    const int mBase = blockIdx.y * BM;
    const int nBase = blockIdx.x * BN;

    const int lr = tid >> 2;
    const int lc = (tid & 3) << 2;

    float acc[2][4][4];
    #pragma unroll
    for (int s=0;s<2;s++)
        #pragma unroll
        for (int n=0;n<4;n++)
            #pragma unroll
            for (int q=0;q<4;q++) acc[s][n][q]=0.f;

    float4 ra[2];
    uint4  rbh, rbl;

    auto ldglob = [&](int kb){
        int k0 = kb*BK;
        #pragma unroll
        for (int p=0;p<2;p++){
            int row = mBase + p*64 + lr;
            ra[p] = *reinterpret_cast<const float4*>(&x[(size_t)row*NIN + k0 + lc]);
        }
        rbh = *reinterpret_cast<const uint4*>(&g_Wxhi[(size_t)(nBase+lr)*NIN + k0 + lc]);
        rbl = *reinterpret_cast<const uint4*>(&g_Wxlo[(size_t)(nBase+lr)*NIN + k0 + lc]);
    };

    ldglob(0);

    const int NKB = NIN/BK;   // 32
    for (int kb = 0; kb < NKB; ++kb){
        #pragma unroll
        for (int p=0;p<2;p++){
            int row = p*64 + lr;
            float v[4] = {ra[p].x, ra[p].y, ra[p].z, ra[p].w};
            #pragma unroll
            for (int q=0;q<4;q++){
                unsigned hi = f2tf32(v[q]);
                As_hi[row*SPAD + lc + q] = hi;
                As_lo[row*SPAD + lc + q] = f2tf32(v[q] - __uint_as_float(hi));
            }
        }
        {
            unsigned bh[4] = {rbh.x, rbh.y, rbh.z, rbh.w};
            unsigned bl[4] = {rbl.x, rbl.y, rbl.z, rbl.w};
            #pragma unroll
            for (int q=0;q<4;q++){
                Bs_hi[lr*SPAD + lc + q] = bh[q];
                Bs_lo[lr*SPAD + lc + q] = bl[q];
            }
        }
        __syncthreads();
        if (kb+1 < NKB) ldglob(kb+1);

        #pragma unroll
        for (int ks=0; ks<2; ++ks){
            const int k8 = ks*8;
            unsigned ah[2][4], al[2][4], bh[4][2], bl[4][2];
            #pragma unroll
            for (int s=0;s<2;s++){
                int r0 = (warpM*32 + s*16 + grp)*SPAD;
                int r1 = (warpM*32 + s*16 + grp + 8)*SPAD;
                ah[s][0] = As_hi[r0 + k8 + tg];
                ah[s][1] = As_hi[r1 + k8 + tg];
                ah[s][2] = As_hi[r0 + k8 + tg + 4];
                ah[s][3] = As_hi[r1 + k8 + tg + 4];
                al[s][0] = As_lo[r0 + k8 + tg];
                al[s][1] = As_lo[r1 + k8 + tg];
                al[s][2] = As_lo[r0 + k8 + tg + 4];
                al[s][3] = As_lo[r1 + k8 + tg + 4];
            }
            #pragma unroll
            for (int n=0;n<4;n++){
                int rb = (warpN*32 + n*8 + grp)*SPAD;
                bh[n][0] = Bs_hi[rb + k8 + tg];
                bh[n][1] = Bs_hi[rb + k8 + tg + 4];
                bl[n][0] = Bs_lo[rb + k8 + tg];
                bl[n][1] = Bs_lo[rb + k8 + tg + 4];
            }
            #pragma unroll
            for (int s=0;s<2;s++)
                #pragma unroll
                for (int n=0;n<4;n++){
                    mma_tf32(acc[s][n], ah[s], bh[n]);
                    mma_tf32(acc[s][n], ah[s], bl[n]);
                    mma_tf32(acc[s][n], al[s], bh[n]);
                }
        }
        __syncthreads();
    }

    // epilogue: write pre[s][b][r] = acc + bias, m = b*SEQ + s
    #pragma unroll
    for (int s=0;s<2;s++){
        #pragma unroll
        for (int rr=0;rr<2;rr++){
            int m = mBase + warpM*32 + s*16 + grp + rr*8;
            int b = m >> 8;            // m / SEQ
            int st = m & (SEQ-1);      // m % SEQ
            size_t base = ((size_t)st*BATCH + b)*FOURH;
            #pragma unroll
            for (int n=0;n<4;n++){
                int col = nBase + warpN*32 + n*8 + tg*2;
                float z0 = acc[s][n][rr*2+0] + g_bperm[col];
                float z1 = acc[s][n][rr*2+1] + g_bperm[col+1];
                *reinterpret_cast<float2*>(&g_pre[base + col]) = make_float2(z0, z1);
            }
        }
    }
}

// =====================================================================================
// Fused step: z = h @ WhP^T + pre[t]; gates; update c, h.   (3xTF32 split, K=1024)
// Grid: (4096/64, 256/128) = (64, 2) = 128 CTAs
// =====================================================================================
__global__ __launch_bounds__(256) void step_kernel(int t)
{
    __shared__ unsigned pool[POOL_WORDS];
    unsigned* As_hi = pool;
    unsigned* As_lo = pool + 2560;
    unsigned* Bs_hi = pool + 5120;
    unsigned* Bs_lo = pool + 6400;
    float*    zsm   = reinterpret_cast<float*>(pool);   // aliased for epilogue

    const int tid  = threadIdx.x;
    const int wid  = tid >> 5;
    const int lane = tid & 31;
    const int warpM = wid & 3;
    const int warpN = wid >> 2;
    const int grp = lane >> 2;
    const int tg  = lane & 3;
    const int mBase = blockIdx.y * BM;
    const int nBase = blockIdx.x * BN;

    const int lr = tid >> 2;
    const int lc = (tid & 3) << 2;

    float acc[2][4][4];
    #pragma unroll
    for (int s=0;s<2;s++)
        #pragma unroll
        for (int n=0;n<4;n++)
            #pragma unroll
            for (int q=0;q<4;q++) acc[s][n][q]=0.f;

    float4 ra[2];
    uint4  rbh, rbl;

    auto ldglob = [&](int kb){
        int k0 = kb*BK;
        #pragma unroll
        for (int p=0;p<2;p++){
            int row = mBase + p*64 + lr;
            ra[p] = *reinterpret_cast<const float4*>(&g_h[row*HD + k0 + lc]);
        }
        rbh = *reinterpret_cast<const uint4*>(&g_Whi[(size_t)(nBase+lr)*HD + k0 + lc]);
        rbl = *reinterpret_cast<const uint4*>(&g_Wlo[(size_t)(nBase+lr)*HD + k0 + lc]);
    };

    ldglob(0);

    const int NKB = HD/BK;   // 64
    for (int kb = 0; kb < NKB; ++kb){
        #pragma unroll
        for (int p=0;p<2;p++){
            int row = p*64 + lr;
            float v[4] = {ra[p].x, ra[p].y, ra[p].z, ra[p].w};
            #pragma unroll
            for (int q=0;q<4;q++){
                unsigned hi = f2tf32(v[q]);
                As_hi[row*SPAD + lc + q] = hi;
                As_lo[row*SPAD + lc + q] = f2tf32(v[q] - __uint_as_float(hi));
            }
        }
        {
            unsigned bh[4] = {rbh.x, rbh.y, rbh.z, rbh.w};
            unsigned bl[4] = {rbl.x, rbl.y, rbl.z, rbl.w};
            #pragma unroll
            for (int q=0;q<4;q++){
                Bs_hi[lr*SPAD + lc + q] = bh[q];
                Bs_lo[lr*SPAD + lc + q] = bl[q];
            }
        }
        __syncthreads();
        if (kb+1 < NKB) ldglob(kb+1);

        #pragma unroll
        for (int ks=0; ks<2; ++ks){
            const int k8 = ks*8;
            unsigned ah[2][4], al[2][4], bh[4][2], bl[4][2];
            #pragma unroll
            for (int s=0;s<2;s++){
                int r0 = (warpM*32 + s*16 + grp)*SPAD;
                int r1 = (warpM*32 + s*16 + grp + 8)*SPAD;
                ah[s][0] = As_hi[r0 + k8 + tg];
                ah[s][1] = As_hi[r1 + k8 + tg];
                ah[s][2] = As_hi[r0 + k8 + tg + 4];
                ah[s][3] = As_hi[r1 + k8 + tg + 4];
                al[s][0] = As_lo[r0 + k8 + tg];
                al[s][1] = As_lo[r1 + k8 + tg];
                al[s][2] = As_lo[r0 + k8 + tg + 4];
                al[s][3] = As_lo[r1 + k8 + tg + 4];
            }
            #pragma unroll
            for (int n=0;n<4;n++){
                int rb = (warpN*32 + n*8 + grp)*SPAD;
                bh[n][0] = Bs_hi[rb + k8 + tg];
                bh[n][1] = Bs_hi[rb + k8 + tg + 4];
                bl[n][0] = Bs_lo[rb + k8 + tg];
                bl[n][1] = Bs_lo[rb + k8 + tg + 4];
            }
            #pragma unroll
            for (int s=0;s<2;s++)
                #pragma unroll
                for (int n=0;n<4;n++){
                    mma_tf32(acc[s][n], ah[s], bh[n]);
                    mma_tf32(acc[s][n], ah[s], bl[n]);
                    mma_tf32(acc[s][n], al[s], bh[n]);
                }
        }
        __syncthreads();
    }
    // after final __syncthreads(), As/Bs dead -> alias pool as z tile

    // stage accumulators into smem z tile [128][ZPAD]
    #pragma unroll
    for (int s=0;s<2;s++){
        int row0 = warpM*32 + s*16 + grp;
        #pragma unroll
        for (int n=0;n<4;n++){
            int col = warpN*32 + n*8 + tg*2;
            *reinterpret_cast<float2*>(&zsm[row0*ZPAD + col]) =
                make_float2(acc[s][n][0], acc[s][n][1]);
            *reinterpret_cast<float2*>(&zsm[(row0+8)*ZPAD + col]) =
                make_float2(acc[s][n][2], acc[s][n][3]);
        }
    }
    __syncthreads();

    // gates: each thread handles 8 (b, j) pairs; CTA covers j in [nBase/4, nBase/4+16)
    const int j0 = nBase >> 2;
    const size_t preRow = (size_t)t*BATCH;
    #pragma unroll
    for (int i=0;i<8;i++){
        int p = i*256 + tid;           // 0..2047
        int row = p >> 4;              // local batch row 0..127
        int jl  = p & 15;              // local j 0..15
        int b   = mBase + row;
        float4 pre4 = *reinterpret_cast<const float4*>(
            &g_pre[(preRow + b)*FOURH + nBase + jl*4]);
        float zg = zsm[row*ZPAD + jl*4 + 0] + pre4.x;
        float zi = zsm[row*ZPAD + jl*4 + 1] + pre4.y;
        float zf = zsm[row*ZPAD + jl*4 + 2] + pre4.z;
        float zo = zsm[row*ZPAD + jl*4 + 3] + pre4.w;
        float gg = tanhf(zg);
        float ii = 1.f/(1.f+expf(-zi));
        float ff = 1.f/(1.f+expf(-zf));
        float oo = 1.f/(1.f+expf(-zo));
        int cidx = b*HD + j0 + jl;
        float c = gg*ii + g_c[cidx]*ff;
        g_c[cidx] = c;
        g_h[cidx] = tanhf(c)*oo;
    }
}

// ---------------- final projection: out = h @ Wp^T + bp (fp32 FFMA) ----------------
__global__ __launch_bounds__(256) void final_proj_kernel(const float* __restrict__ Wp,
                                                         const float* __restrict__ bp,
                                                         float* __restrict__ out)
{
    __shared__ float Hs[64][17];
    __shared__ float Ws[64][17];
    const int tid = threadIdx.x;
    const int mTile = blockIdx.x * 64;
    const int bTile = blockIdx.y * 64;
    const int ty = tid >> 4, tx = tid & 15;
    float acc[4][4];
    #pragma unroll
    for (int i=0;i<4;i++)
        #pragma unroll
        for (int j=0;j<4;j++) acc[i][j]=0.f;

    for (int k0 = 0; k0 < HD; k0 += 16){
        __syncthreads();
        #pragma unroll
        for (int q=0;q<4;q++){
            int lin = q*256 + tid;
            int rr = lin >> 4, cc = lin & 15;
            Hs[rr][cc] = g_h[(bTile + rr)*HD + k0 + cc];
            Ws[rr][cc] = Wp [(mTile + rr)*HD + k0 + cc];
        }
        __syncthreads();
        #pragma unroll
        for (int kk=0; kk<16; ++kk){
            float a[4], bb[4];
            #pragma unroll
            for (int i=0;i<4;i++) a[i]  = Hs[ty*4+i][kk];
            #pragma unroll
            for (int j=0;j<4;j++) bb[j] = Ws[tx*4+j][kk];
            #pragma unroll
            for (int i=0;i<4;i++)
                #pragma unroll
                for (int j=0;j<4;j++) acc[i][j] += a[i]*bb[j];
        }
    }
    #pragma unroll
    for (int i=0;i<4;i++)
        #pragma unroll
        for (int j=0;j<4;j++)
            out[(size_t)(bTile + ty*4 + i)*MOUT + mTile + tx*4 + j] =
                acc[i][j] + bp[mTile + tx*4 + j];
}

// ---------------- launch ----------------
extern "C" void kernel_launch(void* const* d_in, const int* in_sizes, int n_in,
                              void* d_out, int out_size)
{
    const float* x    = (const float*)d_in[0];
    const float* Wgx  = (const float*)d_in[1];
    const float* bgx  = (const float*)d_in[2];
    const float* Wgh  = (const float*)d_in[3];
    const float* Wix  = (const float*)d_in[4];
    const float* bix  = (const float*)d_in[5];
    const float* Wih  = (const float*)d_in[6];
    const float* Wfx  = (const float*)d_in[7];
    const float* bfx  = (const float*)d_in[8];
    const float* Wfh  = (const float*)d_in[9];
    const float* Wox  = (const float*)d_in[10];
    const float* box_ = (const float*)d_in[11];
    const float* Woh  = (const float*)d_in[12];
    const float* Wp   = (const float*)d_in[13];
    const float* bp   = (const float*)d_in[14];
    float* out = (float*)d_out;

    zero_state_kernel<<<(BATCH*HD + 255)/256, 256>>>();
    prep_wh_kernel<<<(FOURH*HD + 255)/256, 256>>>(Wgh, Wih, Wfh, Woh);
    prep_wx_kernel<<<(FOURH*NIN + 255)/256, 256>>>(Wgx, Wix, Wfx, Wox,
                                                   bgx, bix, bfx, box_);

    // hoisted input projection over all timesteps
    input_proj_kernel<<<dim3(FOURH/BN, (BATCH*SEQ)/BM), 256>>>(x);

    // serial recurrence with fused gates
    dim3 gGrid(FOURH/BN, BATCH/BM);   // (64, 2) = 128 CTAs
    for (int t = 0; t < SEQ; ++t){
        step_kernel<<<gGrid, 256>>>(t);
    }

    final_proj_kernel<<<dim3(MOUT/64, BATCH/64), 256>>>(Wp, bp, out);
}

// round 12
// speedup vs baseline: 2.3910x; 2.3910x over previous
#include <cuda_runtime.h>
#include <cuda_bf16.h>
#include <math.h>

#define BATCH 256
#define SEQ   256
#define NIN   512
#define HD    1024
#define MOUT  512
#define FOURH (4*HD)          // 4096

// ---------------- static device scratch (no runtime allocation allowed) ----------------
__device__ float         g_h[BATCH*HD];               // hidden fp32 (for final proj)
__device__ float         g_c[BATCH*HD];               // cell state
__device__ __nv_bfloat16 g_hhi[BATCH*HD];             // bf16 hi of h
__device__ __nv_bfloat16 g_hlo[BATCH*HD];             // bf16 lo of h
__device__ float         g_pre[(size_t)SEQ*BATCH*FOURH];   // x-projections+bias [s][b][r], r=j*4+gate
__device__ __nv_bfloat16 g_Whi[FOURH*HD];             // permuted Wh hi  [r][k]
__device__ __nv_bfloat16 g_Wlo[FOURH*HD];             // permuted Wh lo
__device__ __nv_bfloat16 g_Wxhi[FOURH*NIN];           // permuted Wx hi [r][k]
__device__ __nv_bfloat16 g_Wxlo[FOURH*NIN];           // permuted Wx lo
__device__ __nv_bfloat16 g_xhi[(size_t)BATCH*SEQ*NIN];// x split hi  [m][k], m=b*SEQ+s
__device__ __nv_bfloat16 g_xlo[(size_t)BATCH*SEQ*NIN];// x split lo
__device__ float         g_bperm[FOURH];              // permuted biases

// ---------------- asm helpers ----------------
__device__ __forceinline__ void ldsm4(unsigned r[4], unsigned addr){
    asm volatile("ldmatrix.sync.aligned.m8n8.x4.shared.b16 {%0,%1,%2,%3}, [%4];"
        : "=r"(r[0]),"=r"(r[1]),"=r"(r[2]),"=r"(r[3]) : "r"(addr));
}
__device__ __forceinline__ void mma_bf16(float c[4], const unsigned a[4], const unsigned b[2]){
    asm volatile("mma.sync.aligned.m16n8k16.row.col.f32.bf16.bf16.f32 "
        "{%0,%1,%2,%3}, {%4,%5,%6,%7}, {%8,%9}, {%0,%1,%2,%3};"
        : "+f"(c[0]),"+f"(c[1]),"+f"(c[2]),"+f"(c[3])
        : "r"(a[0]),"r"(a[1]),"r"(a[2]),"r"(a[3]),"r"(b[0]),"r"(b[1]));
}
__device__ __forceinline__ void cp16(unsigned saddr, const void* gptr){
    asm volatile("cp.async.cg.shared.global [%0], [%1], 16;" :: "r"(saddr), "l"(gptr));
}
__device__ __forceinline__ void cp_commit(){ asm volatile("cp.async.commit_group;"); }
__device__ __forceinline__ void cp_waitall(){ asm volatile("cp.async.wait_all;" ::: "memory"); }

__device__ __forceinline__ void bsplit(float v, __nv_bfloat16 &hi, __nv_bfloat16 &lo){
    hi = __float2bfloat16(v);
    lo = __float2bfloat16(v - __bfloat162float(hi));
}

// ---------------- state init ----------------
__global__ void zero_state_kernel(){
    int idx = blockIdx.x*blockDim.x + threadIdx.x;
    if (idx < BATCH*HD){
        g_h[idx] = 0.f; g_c[idx] = 0.f;
        g_hhi[idx] = __float2bfloat16(0.f);
        g_hlo[idx] = __float2bfloat16(0.f);
    }
}

// ---------------- weight prep: permute rows r=j*4+gate, split to bf16 hi/lo ----------------
__global__ void prep_wh_kernel(
    const float* __restrict__ Wgh, const float* __restrict__ Wih,
    const float* __restrict__ Wfh, const float* __restrict__ Woh)
{
    int idx = blockIdx.x*blockDim.x + threadIdx.x;
    if (idx >= FOURH*HD) return;
    int r = idx >> 10;
    int k = idx & (HD-1);
    int j = r >> 2;
    int gate = r & 3;
    const float* W = (gate==0)?Wgh:(gate==1)?Wih:(gate==2)?Wfh:Woh;
    float w = W[j*HD + k];
    __nv_bfloat16 hi, lo; bsplit(w, hi, lo);
    g_Whi[idx] = hi; g_Wlo[idx] = lo;
}

__global__ void prep_wx_kernel(
    const float* __restrict__ Wgx, const float* __restrict__ Wix,
    const float* __restrict__ Wfx, const float* __restrict__ Wox,
    const float* __restrict__ bg,  const float* __restrict__ bi,
    const float* __restrict__ bf,  const float* __restrict__ bo)
{
    int idx = blockIdx.x*blockDim.x + threadIdx.x;
    if (idx >= FOURH*NIN) return;
    int r = idx >> 9;
    int k = idx & (NIN-1);
    int j = r >> 2;
    int gate = r & 3;
    const float* W = (gate==0)?Wgx:(gate==1)?Wix:(gate==2)?Wfx:Wox;
    float w = W[j*NIN + k];
    __nv_bfloat16 hi, lo; bsplit(w, hi, lo);
    g_Wxhi[idx] = hi; g_Wxlo[idx] = lo;
    if (k == 0){
        const float* B = (gate==0)?bg:(gate==1)?bi:(gate==2)?bf:bo;
        g_bperm[r] = B[j];
    }
}

__global__ void prep_x_kernel(const float* __restrict__ x){
    size_t idx = (size_t)blockIdx.x*blockDim.x + threadIdx.x;
    if (idx >= (size_t)BATCH*SEQ*NIN) return;
    __nv_bfloat16 hi, lo; bsplit(x[idx], hi, lo);
    g_xhi[idx] = hi; g_xlo[idx] = lo;
}

// ---------------- shared gemm mainloop (BM=128, BN=64, BK=32 bf16, double-buffered) ----------------
// smem stage layout (bytes): Ah[0,8192) Al[8192,16384) Bh[16384,20480) Bl[20480,24576)
// rows stored 64B wide with 16B-chunk XOR swizzle: off = row*64 + ((c ^ ((row>>1)&3))<<4)
#define STAGE_BYTES 24576
#define AH_OFF 0
#define AL_OFF 8192
#define BH_OFF 16384
#define BL_OFF 20480
#define BKB 32
#define ZPAD 68

template<int KD>
__device__ __forceinline__ void gemm_bf16x3(
    const __nv_bfloat16* __restrict__ Ah, const __nv_bfloat16* __restrict__ Al,
    const __nv_bfloat16* __restrict__ Bh, const __nv_bfloat16* __restrict__ Bl,
    int mBase, int nBase, unsigned smemU, float acc[2][4][4])
{
    const int tid   = threadIdx.x;
    const int lane  = tid & 31;
    const int wid   = tid >> 5;
    const int warpM = wid & 3;       // 4 warps along M (32 rows each)
    const int wN    = wid >> 2;      // 2 warps along N (32 cols each)
    const int q     = lane >> 3;     // ldmatrix quad
    const int r8    = lane & 7;

    const int ar0 = tid >> 2;        // cp.async row (0..63)
    const int ac  = tid & 3;         // cp.async chunk

    auto issue = [&](int kb){
        unsigned sb = smemU + (unsigned)(kb & 1) * STAGE_BYTES;
        int k0 = kb * BKB;
        #pragma unroll
        for (int i=0;i<2;i++){
            int row = ar0 + i*64;
            unsigned d = sb + row*64 + ((unsigned)(ac ^ ((row>>1)&3))<<4);
            cp16(d + AH_OFF, Ah + (size_t)(mBase+row)*KD + k0 + ac*8);
            cp16(d + AL_OFF, Al + (size_t)(mBase+row)*KD + k0 + ac*8);
        }
        {
            int row = ar0;
            unsigned d = sb + row*64 + ((unsigned)(ac ^ ((row>>1)&3))<<4);
            cp16(d + BH_OFF, Bh + (size_t)(nBase+row)*KD + k0 + ac*8);
            cp16(d + BL_OFF, Bl + (size_t)(nBase+row)*KD + k0 + ac*8);
        }
        cp_commit();
    };

    issue(0);
    const int NKB = KD / BKB;
    #pragma unroll 1
    for (int kb = 0; kb < NKB; ++kb){
        cp_waitall();
        __syncthreads();
        if (kb + 1 < NKB) issue(kb + 1);
        unsigned sb = smemU + (unsigned)(kb & 1) * STAGE_BYTES;
        #pragma unroll
        for (int ks = 0; ks < 2; ++ks){
            unsigned a_hi[2][4], a_lo[2][4], b_hi[2][4], b_lo[2][4];
            #pragma unroll
            for (int mt=0; mt<2; ++mt){
                int row = warpM*32 + mt*16 + (q&1)*8 + r8;
                int kc  = ks*2 + (q>>1);
                unsigned ad = sb + row*64 + ((unsigned)(kc ^ ((row>>1)&3))<<4);
                ldsm4(a_hi[mt], ad + AH_OFF);
                ldsm4(a_lo[mt], ad + AL_OFF);
            }
            #pragma unroll
            for (int np=0; np<2; ++np){
                int row = wN*32 + np*16 + (q>>1)*8 + r8;
                int kc  = ks*2 + (q&1);
                unsigned bd = sb + row*64 + ((unsigned)(kc ^ ((row>>1)&3))<<4);
                ldsm4(b_hi[np], bd + BH_OFF);
                ldsm4(b_lo[np], bd + BL_OFF);
            }
            #pragma unroll
            for (int mt=0; mt<2; ++mt)
                #pragma unroll
                for (int nt=0; nt<4; ++nt){
                    const unsigned* bh = &b_hi[nt>>1][(nt&1)*2];
                    const unsigned* bl = &b_lo[nt>>1][(nt&1)*2];
                    mma_bf16(acc[mt][nt], a_hi[mt], bh);   // hi*hi
                    mma_bf16(acc[mt][nt], a_hi[mt], bl);   // hi*lo
                    mma_bf16(acc[mt][nt], a_lo[mt], bh);   // lo*hi
                }
        }
    }
    __syncthreads();   // before caller aliases smem
}

// =====================================================================================
// Fused step: z = h @ WhP^T + pre[t]; gates; update c, h (+bf16 split of h)
// Grid: (4096/64, 256/128) = (64, 2)
// =====================================================================================
__global__ __launch_bounds__(256) void step_kernel(int t)
{
    __shared__ __align__(16) unsigned char pool[49152];
    unsigned smemU = (unsigned)__cvta_generic_to_shared(pool);
    const int tid  = threadIdx.x;
    const int lane = tid & 31;
    const int wid  = tid >> 5;
    const int warpM = wid & 3;
    const int wN    = wid >> 2;
    const int grp = lane >> 2;
    const int tg  = lane & 3;
    const int mBase = blockIdx.y * 128;
    const int nBase = blockIdx.x * 64;

    float acc[2][4][4];
    #pragma unroll
    for (int a=0;a<2;a++)
        #pragma unroll
        for (int b=0;b<4;b++)
            #pragma unroll
            for (int c=0;c<4;c++) acc[a][b][c]=0.f;

    gemm_bf16x3<HD>(g_hhi, g_hlo, g_Whi, g_Wlo, mBase, nBase, smemU, acc);

    // stage accumulators into smem z tile [128][ZPAD] (aliased over pipeline pool)
    float* zsm = reinterpret_cast<float*>(pool);
    #pragma unroll
    for (int mt=0; mt<2; ++mt){
        int row0 = warpM*32 + mt*16 + grp;
        #pragma unroll
        for (int nt=0; nt<4; ++nt){
            int col = wN*32 + nt*8 + tg*2;
            *reinterpret_cast<float2*>(&zsm[row0*ZPAD + col]) =
                make_float2(acc[mt][nt][0], acc[mt][nt][1]);
            *reinterpret_cast<float2*>(&zsm[(row0+8)*ZPAD + col]) =
                make_float2(acc[mt][nt][2], acc[mt][nt][3]);
        }
    }
    __syncthreads();

    // gates: CTA covers j in [nBase/4, nBase/4+16), batch rows [mBase, mBase+128)
    const int j0 = nBase >> 2;
    const size_t preRow = (size_t)t*BATCH;
    #pragma unroll
    for (int i=0;i<8;i++){
        int p = i*256 + tid;
        int row = p >> 4;
        int jl  = p & 15;
        int b   = mBase + row;
        float4 pre4 = *reinterpret_cast<const float4*>(
            &g_pre[(preRow + b)*FOURH + nBase + jl*4]);
        float zg = zsm[row*ZPAD + jl*4 + 0] + pre4.x;
        float zi = zsm[row*ZPAD + jl*4 + 1] + pre4.y;
        float zf = zsm[row*ZPAD + jl*4 + 2] + pre4.z;
        float zo = zsm[row*ZPAD + jl*4 + 3] + pre4.w;
        float gg = tanhf(zg);
        float ii = 1.f/(1.f+expf(-zi));
        float ff = 1.f/(1.f+expf(-zf));
        float oo = 1.f/(1.f+expf(-zo));
        int cidx = b*HD + j0 + jl;
        float c = gg*ii + g_c[cidx]*ff;
        g_c[cidx] = c;
        float h = tanhf(c)*oo;
        g_h[cidx] = h;
        __nv_bfloat16 hi, lo; bsplit(h, hi, lo);
        g_hhi[cidx] = hi;
        g_hlo[cidx] = lo;
    }
}

// =====================================================================================
// Input projection: pre[s][b][r] = x[m] @ WxP^T + bperm ; m = b*SEQ+s
// Grid: (4096/64, 65536/128) = (64, 512)
// =====================================================================================
__global__ __launch_bounds__(256) void input_proj_kernel()
{
    __shared__ __align__(16) unsigned char pool[49152];
    unsigned smemU = (unsigned)__cvta_generic_to_shared(pool);
    const int tid  = threadIdx.x;
    const int lane = tid & 31;
    const int wid  = tid >> 5;
    const int warpM = wid & 3;
    const int wN    = wid >> 2;
    const int grp = lane >> 2;
    const int tg  = lane & 3;
    const int mBase = blockIdx.y * 128;
    const int nBase = blockIdx.x * 64;

    float acc[2][4][4];
    #pragma unroll
    for (int a=0;a<2;a++)
        #pragma unroll
        for (int b=0;b<4;b++)
            #pragma unroll
            for (int c=0;c<4;c++) acc[a][b][c]=0.f;

    gemm_bf16x3<NIN>(g_xhi, g_xlo, g_Wxhi, g_Wxlo, mBase, nBase, smemU, acc);

    // epilogue: write pre with bias; m = b*SEQ + s
    #pragma unroll
    for (int mt=0; mt<2; ++mt){
        #pragma unroll
        for (int rr=0; rr<2; ++rr){
            int m = mBase + warpM*32 + mt*16 + grp + rr*8;
            int b  = m >> 8;
            int st = m & (SEQ-1);
            size_t base = ((size_t)st*BATCH + b)*FOURH;
            #pragma unroll
            for (int nt=0; nt<4; ++nt){
                int col = nBase + wN*32 + nt*8 + tg*2;
                float z0 = acc[mt][nt][rr*2+0] + g_bperm[col];
                float z1 = acc[mt][nt][rr*2+1] + g_bperm[col+1];
                *reinterpret_cast<float2*>(&g_pre[base + col]) = make_float2(z0, z1);
            }
        }
    }
}

// ---------------- final projection: out = h @ Wp^T + bp (fp32 FFMA) ----------------
__global__ __launch_bounds__(256) void final_proj_kernel(const float* __restrict__ Wp,
                                                         const float* __restrict__ bp,
                                                         float* __restrict__ out)
{
    __shared__ float Hs[64][17];
    __shared__ float Ws[64][17];
    const int tid = threadIdx.x;
    const int mTile = blockIdx.x * 64;
    const int bTile = blockIdx.y * 64;
    const int ty = tid >> 4, tx = tid & 15;
    float acc[4][4];
    #pragma unroll
    for (int i=0;i<4;i++)
        #pragma unroll
        for (int j=0;j<4;j++) acc[i][j]=0.f;

    for (int k0 = 0; k0 < HD; k0 += 16){
        __syncthreads();
        #pragma unroll
        for (int q=0;q<4;q++){
            int lin = q*256 + tid;
            int rr = lin >> 4, cc = lin & 15;
            Hs[rr][cc] = g_h[(bTile + rr)*HD + k0 + cc];
            Ws[rr][cc] = Wp [(mTile + rr)*HD + k0 + cc];
        }
        __syncthreads();
        #pragma unroll
        for (int kk=0; kk<16; ++kk){
            float a[4], bb[4];
            #pragma unroll
            for (int i=0;i<4;i++) a[i]  = Hs[ty*4+i][kk];
            #pragma unroll
            for (int j=0;j<4;j++) bb[j] = Ws[tx*4+j][kk];
            #pragma unroll
            for (int i=0;i<4;i++)
                #pragma unroll
                for (int j=0;j<4;j++) acc[i][j] += a[i]*bb[j];
        }
    }
    #pragma unroll
    for (int i=0;i<4;i++)
        #pragma unroll
        for (int j=0;j<4;j++)
            out[(size_t)(bTile + ty*4 + i)*MOUT + mTile + tx*4 + j] =
                acc[i][j] + bp[mTile + tx*4 + j];
}

// ---------------- launch ----------------
extern "C" void kernel_launch(void* const* d_in, const int* in_sizes, int n_in,
                              void* d_out, int out_size)
{
    const float* x    = (const float*)d_in[0];
    const float* Wgx  = (const float*)d_in[1];
    const float* bgx  = (const float*)d_in[2];
    const float* Wgh  = (const float*)d_in[3];
    const float* Wix  = (const float*)d_in[4];
    const float* bix  = (const float*)d_in[5];
    const float* Wih  = (const float*)d_in[6];
    const float* Wfx  = (const float*)d_in[7];
    const float* bfx  = (const float*)d_in[8];
    const float* Wfh  = (const float*)d_in[9];
    const float* Wox  = (const float*)d_in[10];
    const float* box_ = (const float*)d_in[11];
    const float* Woh  = (const float*)d_in[12];
    const float* Wp   = (const float*)d_in[13];
    const float* bp   = (const float*)d_in[14];
    float* out = (float*)d_out;

    zero_state_kernel<<<(BATCH*HD + 255)/256, 256>>>();
    prep_wh_kernel<<<(FOURH*HD + 255)/256, 256>>>(Wgh, Wih, Wfh, Woh);
    prep_wx_kernel<<<(FOURH*NIN + 255)/256, 256>>>(Wgx, Wix, Wfx, Wox,
                                                   bgx, bix, bfx, box_);
    prep_x_kernel<<<(int)(((size_t)BATCH*SEQ*NIN + 255)/256), 256>>>(x);

    input_proj_kernel<<<dim3(FOURH/64, (BATCH*SEQ)/128), 256>>>();

    dim3 gGrid(FOURH/64, BATCH/128);   // (64, 2) = 128 CTAs
    for (int t = 0; t < SEQ; ++t){
        step_kernel<<<gGrid, 256>>>(t);
    }

    final_proj_kernel<<<dim3(MOUT/64, BATCH/64), 256>>>(Wp, bp, out);
}

// round 16
// speedup vs baseline: 2.4160x; 1.0105x over previous
#include <cuda_runtime.h>
#include <cuda_bf16.h>
#include <math.h>

#define BATCH 256
#define SEQ   256
#define NIN   512
#define HD    1024
#define MOUT  512
#define FOURH (4*HD)          // 4096
#define NCTAS 128             // persistent grid size (64 x 2)

// ---------------- static device scratch (no runtime allocation allowed) ----------------
__device__ float         g_h[BATCH*HD];               // hidden fp32 (for final proj)
__device__ float         g_c[BATCH*HD];               // cell state
__device__ __nv_bfloat16 g_hhi[BATCH*HD];             // bf16 hi of h
__device__ __nv_bfloat16 g_hlo[BATCH*HD];             // bf16 lo of h
__device__ float         g_pre[(size_t)SEQ*BATCH*FOURH];   // x-projections+bias [s][b][r], r=j*4+gate
__device__ __nv_bfloat16 g_Whi[FOURH*HD];             // permuted Wh hi  [r][k]
__device__ __nv_bfloat16 g_Wlo[FOURH*HD];             // permuted Wh lo
__device__ __nv_bfloat16 g_Wxhi[FOURH*NIN];           // permuted Wx hi [r][k]
__device__ __nv_bfloat16 g_Wxlo[FOURH*NIN];           // permuted Wx lo
__device__ __nv_bfloat16 g_xhi[(size_t)BATCH*SEQ*NIN];// x split hi  [m][k], m=b*SEQ+s
__device__ __nv_bfloat16 g_xlo[(size_t)BATCH*SEQ*NIN];// x split lo
__device__ float         g_bperm[FOURH];              // permuted biases
__device__ volatile unsigned g_bar;                   // grid barrier counter (reset per replay)

// ---------------- asm helpers ----------------
__device__ __forceinline__ void ldsm4(unsigned r[4], unsigned addr){
    asm volatile("ldmatrix.sync.aligned.m8n8.x4.shared.b16 {%0,%1,%2,%3}, [%4];"
        : "=r"(r[0]),"=r"(r[1]),"=r"(r[2]),"=r"(r[3]) : "r"(addr));
}
__device__ __forceinline__ void mma_bf16(float c[4], const unsigned a[4], const unsigned b[2]){
    asm volatile("mma.sync.aligned.m16n8k16.row.col.f32.bf16.bf16.f32 "
        "{%0,%1,%2,%3}, {%4,%5,%6,%7}, {%8,%9}, {%0,%1,%2,%3};"
        : "+f"(c[0]),"+f"(c[1]),"+f"(c[2]),"+f"(c[3])
        : "r"(a[0]),"r"(a[1]),"r"(a[2]),"r"(a[3]),"r"(b[0]),"r"(b[1]));
}
__device__ __forceinline__ void cp16(unsigned saddr, const void* gptr){
    asm volatile("cp.async.cg.shared.global [%0], [%1], 16;" :: "r"(saddr), "l"(gptr));
}
__device__ __forceinline__ void cp_commit(){ asm volatile("cp.async.commit_group;"); }
__device__ __forceinline__ void cp_waitall(){ asm volatile("cp.async.wait_all;" ::: "memory"); }

__device__ __forceinline__ void bsplit(float v, __nv_bfloat16 &hi, __nv_bfloat16 &lo){
    hi = __float2bfloat16(v);
    lo = __float2bfloat16(v - __bfloat162float(hi));
}

// ---------------- state init ----------------
__global__ void zero_state_kernel(){
    int idx = blockIdx.x*blockDim.x + threadIdx.x;
    if (idx < BATCH*HD){
        g_h[idx] = 0.f; g_c[idx] = 0.f;
        g_hhi[idx] = __float2bfloat16(0.f);
        g_hlo[idx] = __float2bfloat16(0.f);
    }
    if (idx == 0) g_bar = 0u;
}

// ---------------- weight prep: permute rows r=j*4+gate, split to bf16 hi/lo ----------------
__global__ void prep_wh_kernel(
    const float* __restrict__ Wgh, const float* __restrict__ Wih,
    const float* __restrict__ Wfh, const float* __restrict__ Woh)
{
    int idx = blockIdx.x*blockDim.x + threadIdx.x;
    if (idx >= FOURH*HD) return;
    int r = idx >> 10;
    int k = idx & (HD-1);
    int j = r >> 2;
    int gate = r & 3;
    const float* W = (gate==0)?Wgh:(gate==1)?Wih:(gate==2)?Wfh:Woh;
    float w = W[j*HD + k];
    __nv_bfloat16 hi, lo; bsplit(w, hi, lo);
    g_Whi[idx] = hi; g_Wlo[idx] = lo;
}

__global__ void prep_wx_kernel(
    const float* __restrict__ Wgx, const float* __restrict__ Wix,
    const float* __restrict__ Wfx, const float* __restrict__ Wox,
    const float* __restrict__ bg,  const float* __restrict__ bi,
    const float* __restrict__ bf,  const float* __restrict__ bo)
{
    int idx = blockIdx.x*blockDim.x + threadIdx.x;
    if (idx >= FOURH*NIN) return;
    int r = idx >> 9;
    int k = idx & (NIN-1);
    int j = r >> 2;
    int gate = r & 3;
    const float* W = (gate==0)?Wgx:(gate==1)?Wix:(gate==2)?Wfx:Wox;
    float w = W[j*NIN + k];
    __nv_bfloat16 hi, lo; bsplit(w, hi, lo);
    g_Wxhi[idx] = hi; g_Wxlo[idx] = lo;
    if (k == 0){
        const float* B = (gate==0)?bg:(gate==1)?bi:(gate==2)?bf:bo;
        g_bperm[r] = B[j];
    }
}

__global__ void prep_x_kernel(const float* __restrict__ x){
    size_t idx = (size_t)blockIdx.x*blockDim.x + threadIdx.x;
    if (idx >= (size_t)BATCH*SEQ*NIN) return;
    __nv_bfloat16 hi, lo; bsplit(x[idx], hi, lo);
    g_xhi[idx] = hi; g_xlo[idx] = lo;
}

// ---------------- shared gemm mainloop (BM=128, BN=64, BK=32 bf16, double-buffered) ----------------
// smem stage layout (bytes): Ah[0,8192) Al[8192,16384) Bh[16384,20480) Bl[20480,24576)
// rows stored 64B wide with 16B-chunk XOR swizzle: off = row*64 + ((c ^ ((row>>1)&3))<<4)
#define STAGE_BYTES 24576
#define AH_OFF 0
#define AL_OFF 8192
#define BH_OFF 16384
#define BL_OFF 20480
#define BKB 32
#define ZPAD 68

template<int KD>
__device__ __forceinline__ void gemm_bf16x3(
    const __nv_bfloat16* __restrict__ Ah, const __nv_bfloat16* __restrict__ Al,
    const __nv_bfloat16* __restrict__ Bh, const __nv_bfloat16* __restrict__ Bl,
    int mBase, int nBase, unsigned smemU, float acc[2][4][4])
{
    const int tid   = threadIdx.x;
    const int lane  = tid & 31;
    const int wid   = tid >> 5;
    const int warpM = wid & 3;       // 4 warps along M (32 rows each)
    const int wN    = wid >> 2;      // 2 warps along N (32 cols each)
    const int q     = lane >> 3;     // ldmatrix quad
    const int r8    = lane & 7;

    const int ar0 = tid >> 2;        // cp.async row (0..63)
    const int ac  = tid & 3;         // cp.async chunk

    auto issue = [&](int kb){
        unsigned sb = smemU + (unsigned)(kb & 1) * STAGE_BYTES;
        int k0 = kb * BKB;
        #pragma unroll
        for (int i=0;i<2;i++){
            int row = ar0 + i*64;
            unsigned d = sb + row*64 + ((unsigned)(ac ^ ((row>>1)&3))<<4);
            cp16(d + AH_OFF, Ah + (size_t)(mBase+row)*KD + k0 + ac*8);
            cp16(d + AL_OFF, Al + (size_t)(mBase+row)*KD + k0 + ac*8);
        }
        {
            int row = ar0;
            unsigned d = sb + row*64 + ((unsigned)(ac ^ ((row>>1)&3))<<4);
            cp16(d + BH_OFF, Bh + (size_t)(nBase+row)*KD + k0 + ac*8);
            cp16(d + BL_OFF, Bl + (size_t)(nBase+row)*KD + k0 + ac*8);
        }
        cp_commit();
    };

    issue(0);
    const int NKB = KD / BKB;
    #pragma unroll 1
    for (int kb = 0; kb < NKB; ++kb){
        cp_waitall();
        __syncthreads();
        if (kb + 1 < NKB) issue(kb + 1);
        unsigned sb = smemU + (unsigned)(kb & 1) * STAGE_BYTES;
        #pragma unroll
        for (int ks = 0; ks < 2; ++ks){
            unsigned a_hi[2][4], a_lo[2][4], b_hi[2][4], b_lo[2][4];
            #pragma unroll
            for (int mt=0; mt<2; ++mt){
                int row = warpM*32 + mt*16 + (q&1)*8 + r8;
                int kc  = ks*2 + (q>>1);
                unsigned ad = sb + row*64 + ((unsigned)(kc ^ ((row>>1)&3))<<4);
                ldsm4(a_hi[mt], ad + AH_OFF);
                ldsm4(a_lo[mt], ad + AL_OFF);
            }
            #pragma unroll
            for (int np=0; np<2; ++np){
                int row = wN*32 + np*16 + (q>>1)*8 + r8;
                int kc  = ks*2 + (q&1);
                unsigned bd = sb + row*64 + ((unsigned)(kc ^ ((row>>1)&3))<<4);
                ldsm4(b_hi[np], bd + BH_OFF);
                ldsm4(b_lo[np], bd + BL_OFF);
            }
            #pragma unroll
            for (int mt=0; mt<2; ++mt)
                #pragma unroll
                for (int nt=0; nt<4; ++nt){
                    const unsigned* bh = &b_hi[nt>>1][(nt&1)*2];
                    const unsigned* bl = &b_lo[nt>>1][(nt&1)*2];
                    mma_bf16(acc[mt][nt], a_hi[mt], bh);   // hi*hi
                    mma_bf16(acc[mt][nt], a_hi[mt], bl);   // hi*lo
                    mma_bf16(acc[mt][nt], a_lo[mt], bh);   // lo*hi
                }
        }
    }
    __syncthreads();   // before caller aliases smem
}

// =====================================================================================
// Persistent recurrence kernel: all 256 steps in ONE launch, grid barrier between steps.
// Grid: (64, 2) = 128 CTAs <= 148 SMs -> single wave, all co-resident (barrier safe).
// =====================================================================================
__global__ __launch_bounds__(256) void lstm_persistent_kernel()
{
    __shared__ __align__(16) unsigned char pool[49152];
    unsigned smemU = (unsigned)__cvta_generic_to_shared(pool);
    const int tid  = threadIdx.x;
    const int lane = tid & 31;
    const int wid  = tid >> 5;
    const int warpM = wid & 3;
    const int wN    = wid >> 2;
    const int grp = lane >> 2;
    const int tg  = lane & 3;
    const int mBase = blockIdx.y * 128;
    const int nBase = blockIdx.x * 64;
    const int j0    = nBase >> 2;
    float* zsm = reinterpret_cast<float*>(pool);

    for (int t = 0; t < SEQ; ++t){
        float acc[2][4][4];
        #pragma unroll
        for (int a=0;a<2;a++)
            #pragma unroll
            for (int b=0;b<4;b++)
                #pragma unroll
                for (int c=0;c<4;c++) acc[a][b][c]=0.f;

        gemm_bf16x3<HD>(g_hhi, g_hlo, g_Whi, g_Wlo, mBase, nBase, smemU, acc);

        // stage accumulators into smem z tile [128][ZPAD] (aliased over pipeline pool)
        #pragma unroll
        for (int mt=0; mt<2; ++mt){
            int row0 = warpM*32 + mt*16 + grp;
            #pragma unroll
            for (int nt=0; nt<4; ++nt){
                int col = wN*32 + nt*8 + tg*2;
                *reinterpret_cast<float2*>(&zsm[row0*ZPAD + col]) =
                    make_float2(acc[mt][nt][0], acc[mt][nt][1]);
                *reinterpret_cast<float2*>(&zsm[(row0+8)*ZPAD + col]) =
                    make_float2(acc[mt][nt][2], acc[mt][nt][3]);
            }
        }
        __syncthreads();

        // gates: CTA covers j in [j0, j0+16), batch rows [mBase, mBase+128)
        const size_t preRow = (size_t)t*BATCH;
        #pragma unroll
        for (int i=0;i<8;i++){
            int p = i*256 + tid;
            int row = p >> 4;
            int jl  = p & 15;
            int b   = mBase + row;
            float4 pre4 = *reinterpret_cast<const float4*>(
                &g_pre[(preRow + b)*FOURH + nBase + jl*4]);
            float zg = zsm[row*ZPAD + jl*4 + 0] + pre4.x;
            float zi = zsm[row*ZPAD + jl*4 + 1] + pre4.y;
            float zf = zsm[row*ZPAD + jl*4 + 2] + pre4.z;
            float zo = zsm[row*ZPAD + jl*4 + 3] + pre4.w;
            float gg = tanhf(zg);
            float ii = 1.f/(1.f+expf(-zi));
            float ff = 1.f/(1.f+expf(-zf));
            float oo = 1.f/(1.f+expf(-zo));
            int cidx = b*HD + j0 + jl;
            float c = gg*ii + g_c[cidx]*ff;
            g_c[cidx] = c;
            float h = tanhf(c)*oo;
            g_h[cidx] = h;
            __nv_bfloat16 hi, lo; bsplit(h, hi, lo);
            g_hhi[cidx] = hi;
            g_hlo[cidx] = lo;
        }

        // ---- grid barrier: all h writes visible before any CTA starts step t+1 ----
        __threadfence();
        __syncthreads();
        if (tid == 0){
            atomicAdd((unsigned*)&g_bar, 1u);
            unsigned target = (unsigned)(t + 1) * NCTAS;
            while (g_bar < target) { __nanosleep(64); }
        }
        __syncthreads();
    }
}

// =====================================================================================
// Input projection: pre[s][b][r] = x[m] @ WxP^T + bperm ; m = b*SEQ+s
// Grid: (4096/64, 65536/128) = (64, 512)
// =====================================================================================
__global__ __launch_bounds__(256) void input_proj_kernel()
{
    __shared__ __align__(16) unsigned char pool[49152];
    unsigned smemU = (unsigned)__cvta_generic_to_shared(pool);
    const int tid  = threadIdx.x;
    const int lane = tid & 31;
    const int wid  = tid >> 5;
    const int warpM = wid & 3;
    const int wN    = wid >> 2;
    const int grp = lane >> 2;
    const int tg  = lane & 3;
    const int mBase = blockIdx.y * 128;
    const int nBase = blockIdx.x * 64;

    float acc[2][4][4];
    #pragma unroll
    for (int a=0;a<2;a++)
        #pragma unroll
        for (int b=0;b<4;b++)
            #pragma unroll
            for (int c=0;c<4;c++) acc[a][b][c]=0.f;

    gemm_bf16x3<NIN>(g_xhi, g_xlo, g_Wxhi, g_Wxlo, mBase, nBase, smemU, acc);

    // epilogue: write pre with bias; m = b*SEQ + s
    #pragma unroll
    for (int mt=0; mt<2; ++mt){
        #pragma unroll
        for (int rr=0; rr<2; ++rr){
            int m = mBase + warpM*32 + mt*16 + grp + rr*8;
            int b  = m >> 8;
            int st = m & (SEQ-1);
            size_t base = ((size_t)st*BATCH + b)*FOURH;
            #pragma unroll
            for (int nt=0; nt<4; ++nt){
                int col = nBase + wN*32 + nt*8 + tg*2;
                float z0 = acc[mt][nt][rr*2+0] + g_bperm[col];
                float z1 = acc[mt][nt][rr*2+1] + g_bperm[col+1];
                *reinterpret_cast<float2*>(&g_pre[base + col]) = make_float2(z0, z1);
            }
        }
    }
}

// ---------------- final projection: out = h @ Wp^T + bp (fp32 FFMA) ----------------
__global__ __launch_bounds__(256) void final_proj_kernel(const float* __restrict__ Wp,
                                                         const float* __restrict__ bp,
                                                         float* __restrict__ out)
{
    __shared__ float Hs[64][17];
    __shared__ float Ws[64][17];
    const int tid = threadIdx.x;
    const int mTile = blockIdx.x * 64;
    const int bTile = blockIdx.y * 64;
    const int ty = tid >> 4, tx = tid & 15;
    float acc[4][4];
    #pragma unroll
    for (int i=0;i<4;i++)
        #pragma unroll
        for (int j=0;j<4;j++) acc[i][j]=0.f;

    for (int k0 = 0; k0 < HD; k0 += 16){
        __syncthreads();
        #pragma unroll
        for (int q=0;q<4;q++){
            int lin = q*256 + tid;
            int rr = lin >> 4, cc = lin & 15;
            Hs[rr][cc] = g_h[(bTile + rr)*HD + k0 + cc];
            Ws[rr][cc] = Wp [(mTile + rr)*HD + k0 + cc];
        }
        __syncthreads();
        #pragma unroll
        for (int kk=0; kk<16; ++kk){
            float a[4], bb[4];
            #pragma unroll
            for (int i=0;i<4;i++) a[i]  = Hs[ty*4+i][kk];
            #pragma unroll
            for (int j=0;j<4;j++) bb[j] = Ws[tx*4+j][kk];
            #pragma unroll
            for (int i=0;i<4;i++)
                #pragma unroll
                for (int j=0;j<4;j++) acc[i][j] += a[i]*bb[j];
        }
    }
    #pragma unroll
    for (int i=0;i<4;i++)
        #pragma unroll
        for (int j=0;j<4;j++)
            out[(size_t)(bTile + ty*4 + i)*MOUT + mTile + tx*4 + j] =
                acc[i][j] + bp[mTile + tx*4 + j];
}

// ---------------- launch ----------------
extern "C" void kernel_launch(void* const* d_in, const int* in_sizes, int n_in,
                              void* d_out, int out_size)
{
    const float* x    = (const float*)d_in[0];
    const float* Wgx  = (const float*)d_in[1];
    const float* bgx  = (const float*)d_in[2];
    const float* Wgh  = (const float*)d_in[3];
    const float* Wix  = (const float*)d_in[4];
    const float* bix  = (const float*)d_in[5];
    const float* Wih  = (const float*)d_in[6];
    const float* Wfx  = (const float*)d_in[7];
    const float* bfx  = (const float*)d_in[8];
    const float* Wfh  = (const float*)d_in[9];
    const float* Wox  = (const float*)d_in[10];
    const float* box_ = (const float*)d_in[11];
    const float* Woh  = (const float*)d_in[12];
    const float* Wp   = (const float*)d_in[13];
    const float* bp   = (const float*)d_in[14];
    float* out = (float*)d_out;

    zero_state_kernel<<<(BATCH*HD + 255)/256, 256>>>();
    prep_wh_kernel<<<(FOURH*HD + 255)/256, 256>>>(Wgh, Wih, Wfh, Woh);
    prep_wx_kernel<<<(FOURH*NIN + 255)/256, 256>>>(Wgx, Wix, Wfx, Wox,
                                                   bgx, bix, bfx, box_);
    prep_x_kernel<<<(int)(((size_t)BATCH*SEQ*NIN + 255)/256), 256>>>(x);

    input_proj_kernel<<<dim3(FOURH/64, (BATCH*SEQ)/128), 256>>>();

    // one persistent launch replaces 256 step launches
    lstm_persistent_kernel<<<dim3(FOURH/64, BATCH/128), 256>>>();

    final_proj_kernel<<<dim3(MOUT/64, BATCH/64), 256>>>(Wp, bp, out);
}